// round 4
// baseline (speedup 1.0000x reference)
#include <cuda_runtime.h>
#include <cuda_bf16.h>
#include <cstdint>
#include <cstddef>

// Problem constants
#define BATCH 32
#define NT    256
#define NS    4096
#define CDIM  256
#define TOPKN 32
#define NWIN  64      // 8x8 windows
#define WTOK  64      // tokens per window (8x8)

// ---------------- device scratch (no allocations allowed) ----------------
__device__ float g_WdT[CDIM * CDIM];   // WdT[k*256 + o] = Wd[o*256 + k]
__device__ float g_WuT[CDIM * CDIM];   // WuT[c*256 + o] = Wu[o*256 + c]
__device__ float g_zmax[BATCH * CDIM];
__device__ float g_simw[BATCH * NWIN];
__device__ int   g_idx[BATCH * TOPKN];

// ---------------- K0: transpose both weight matrices ----------------
__global__ void k_transpose(const float* __restrict__ Wd,
                            const float* __restrict__ Wu) {
    const int i = blockIdx.x * 256 + threadIdx.x;  // i = k*256 + o
    const int k = i >> 8;
    const int o = i & 255;
    g_WdT[i] = Wd[o * 256 + k];
    g_WuT[i] = Wu[o * 256 + k];
}

// ---------------- K1: z_max over Nt ----------------
__global__ void k_zmax(const float* __restrict__ z) {
    const int b = blockIdx.x;
    const int c = threadIdx.x;
    const float* zb = z + (size_t)b * NT * CDIM + c;
    float m = zb[0];
    #pragma unroll 8
    for (int n = 1; n < NT; ++n) m = fmaxf(m, zb[(size_t)n * CDIM]);
    g_zmax[b * CDIM + c] = m;
}

// ---------------- K2: per-window mean similarity ----------------
// grid: B*64 blocks, 256 threads (8 warps, each warp does 8 tokens)
__global__ void k_sim(const float* __restrict__ x) {
    const int bw = blockIdx.x;
    const int b = bw >> 6;
    const int win = bw & 63;
    const int wh = win >> 3, ww = win & 7;

    __shared__ float zm[CDIM];
    __shared__ float tok[WTOK];

    const int tid = threadIdx.x;
    zm[tid] = g_zmax[b * CDIM + tid];
    __syncthreads();

    const int w = tid >> 5, l = tid & 31;
    const float* xb = x + ((size_t)b * NS + (size_t)wh * 512 + (size_t)ww * 8) * CDIM;
    const float4* zm4 = (const float4*)zm;
    const float4 z0 = zm4[2 * l];
    const float4 z1 = zm4[2 * l + 1];

    #pragma unroll
    for (int m = 0; m < 8; ++m) {
        // token (i=w, j=m) inside the window
        const float4* row = (const float4*)(xb + (size_t)(w * 64 + m) * CDIM);
        const float4 v0 = row[2 * l];
        const float4 v1 = row[2 * l + 1];
        float a = v0.x * z0.x + v0.y * z0.y + v0.z * z0.z + v0.w * z0.w
                + v1.x * z1.x + v1.y * z1.y + v1.z * z1.z + v1.w * z1.w;
        #pragma unroll
        for (int off = 16; off; off >>= 1) a += __shfl_xor_sync(0xffffffffu, a, off);
        if (l == 0) tok[w * 8 + m] = a;
    }
    __syncthreads();
    if (tid < 32) {
        float v = tok[tid] + tok[tid + 32];
        #pragma unroll
        for (int off = 16; off; off >>= 1) v += __shfl_xor_sync(0xffffffffu, v, off);
        if (tid == 0) g_simw[b * NWIN + win] = v * (1.0f / (256.0f * 64.0f));
    }
}

// ---------------- K3: top-k (descending value, tie -> lower index) ----------------
__global__ void k_topk() {
    const int b = blockIdx.x;
    const int t = threadIdx.x;            // 64 threads
    __shared__ float v[NWIN];
    v[t] = g_simw[b * NWIN + t];
    __syncthreads();
    if (t < 32) {
        for (int k = 0; k < TOPKN; ++k) {
            float a = v[t], c = v[t + 32];
            float bestv; int besti;
            if (a >= c) { bestv = a; besti = t; } else { bestv = c; besti = t + 32; }
            #pragma unroll
            for (int off = 16; off; off >>= 1) {
                float ov = __shfl_xor_sync(0xffffffffu, bestv, off);
                int   oi = __shfl_xor_sync(0xffffffffu, besti, off);
                if (ov > bestv || (ov == bestv && oi < besti)) { bestv = ov; besti = oi; }
            }
            besti = __shfl_sync(0xffffffffu, besti, 0);
            if (t == 0) {
                g_idx[b * TOPKN + k] = besti;
                v[besti] = -__int_as_float(0x7f800000);  // -inf
            }
            __syncwarp();
        }
    }
}

// ---------------- fused per-window GEMM helper ----------------
// Thread `o` computes output column o over 64 rows, reduction over 256 channels.
// A in smem is column(k)-major with XOR-swizzled float4 groups:
//   element (k, r) at word  k*64 + (((r>>2) ^ (k&15)) << 2) + (r&3)
// acc[m] packs rows (2m, 2m+1) as f32x2 in a 64-bit register.
__device__ __forceinline__ void gemm_col(const float* sm,
                                         const float* __restrict__ Wt,
                                         int o,
                                         unsigned long long acc[32]) {
    #pragma unroll
    for (int m = 0; m < 32; ++m) acc[m] = 0ULL;
    const float* wcol = Wt + o;
    #pragma unroll 1
    for (int kb = 0; kb < 16; ++kb) {
        const float* smb = sm + (kb << 10);            // 16 columns * 64 floats
        const float* wb  = wcol + (kb << 12);          // 16 rows * 256
        #pragma unroll
        for (int kq = 0; kq < 16; ++kq) {
            const float wv = __ldg(wb + (kq << 8));
            unsigned long long w2;
            asm("mov.b64 %0, {%1,%1};" : "=l"(w2) : "f"(wv));
            const float* colp = smb + (kq << 6);
            #pragma unroll
            for (int f = 0; f < 16; ++f) {
                const ulonglong2 a =
                    *reinterpret_cast<const ulonglong2*>(colp + ((f ^ kq) << 2));
                asm("fma.rn.f32x2 %0, %1, %2, %0;" : "+l"(acc[2 * f])     : "l"(a.x), "l"(w2));
                asm("fma.rn.f32x2 %0, %1, %2, %0;" : "+l"(acc[2 * f + 1]) : "l"(a.y), "l"(w2));
            }
        }
    }
}

__device__ __forceinline__ int swz(int r, int sw) {
    return ((((r >> 2) ^ sw) << 2) | (r & 3));
}

// ---------------- K4: gather + GEMM1 + shift + GEMM2 + residual ----------------
__global__ void __launch_bounds__(256, 2) k_main(const float* __restrict__ x,
                                                 const float* __restrict__ bd,
                                                 const float* __restrict__ bu,
                                                 float* __restrict__ out) {
    extern __shared__ float sm[];   // 64 cols-of-k? no: 256 columns(k) x 64 rows = 16384 floats
    const int g = blockIdx.x;
    const int b = g >> 5;
    const int kk = g & 31;
    const int win = g_idx[b * TOPKN + kk];
    const int wh = win >> 3, ww = win & 7;
    const int o = threadIdx.x;          // output channel / smem column owner
    const int sw = o & 15;

    const float* xb = x + ((size_t)b * NS + (size_t)wh * 512 + (size_t)ww * 8) * CDIM;

    // ---- gather xe window (64 x 256) into swizzled k-major smem ----
    #pragma unroll
    for (int r = 0; r < 64; ++r) {
        const int goff = ((r >> 3) * 64 + (r & 7)) * CDIM;  // compile-time per r
        const float v = __ldg(xb + goff + o);
        sm[(o << 6) + swz(r, sw)] = v;
    }
    __syncthreads();

    unsigned long long acc[32];

    // ---- GEMM1: t[:, o] = xe @ Wd^T ----
    gemm_col(sm, g_WdT, o, acc);

    // ---- t = acc + bd; spatial shift by channel group; write back to sm ----
    const float bdv = __ldg(bd + o);
    float t[64];
    #pragma unroll
    for (int m = 0; m < 32; ++m) {
        float lo, hi;
        asm("mov.b64 {%0,%1}, %2;" : "=f"(lo), "=f"(hi) : "l"(acc[m]));
        t[2 * m]     = lo + bdv;
        t[2 * m + 1] = hi + bdv;
    }
    __syncthreads();   // all GEMM1 reads of sm finished before overwrite

    const int grp = o >> 6;   // uniform within a warp (no divergence)
    if (grp == 0) {
        // s0[i,j] = t[i, j+1] (j<7 else 0)
        #pragma unroll
        for (int r = 0; r < 64; ++r) {
            float v = 0.0f;
            if ((r & 7) != 7) v = t[((r & 7) != 7) ? (r + 1) : 0];
            sm[(o << 6) + swz(r, sw)] = v;
        }
    } else if (grp == 1) {
        // s1[i,j] = t[i, j-1] (j>0 else 0)
        #pragma unroll
        for (int r = 0; r < 64; ++r) {
            float v = 0.0f;
            if ((r & 7) != 0) v = t[((r & 7) != 0) ? (r - 1) : 0];
            sm[(o << 6) + swz(r, sw)] = v;
        }
    } else if (grp == 2) {
        // s2[i,j] = t[i+1, j] (i<7 else 0)
        #pragma unroll
        for (int r = 0; r < 64; ++r) {
            float v = 0.0f;
            if (r < 56) v = t[(r < 56) ? (r + 8) : 0];
            sm[(o << 6) + swz(r, sw)] = v;
        }
    } else {
        // s3[i,j] = t[i-1, j] (i>0 else 0)
        #pragma unroll
        for (int r = 0; r < 64; ++r) {
            float v = 0.0f;
            if (r >= 8) v = t[(r >= 8) ? (r - 8) : 0];
            sm[(o << 6) + swz(r, sw)] = v;
        }
    }
    __syncthreads();

    // ---- GEMM2: up[:, o] = sh @ Wu^T ----
    gemm_col(sm, g_WuT, o, acc);

    // ---- epilogue: out = xe + up + bu ----
    const float buv = __ldg(bu + o);
    float* ob = out + ((size_t)b * (TOPKN * WTOK) + (size_t)kk * WTOK) * CDIM + o;
    #pragma unroll
    for (int m = 0; m < 32; ++m) {
        float lo, hi;
        asm("mov.b64 {%0,%1}, %2;" : "=f"(lo), "=f"(hi) : "l"(acc[m]));
        const int r0 = 2 * m, r1 = 2 * m + 1;
        const int g0off = ((r0 >> 3) * 64 + (r0 & 7)) * CDIM;
        const int g1off = ((r1 >> 3) * 64 + (r1 & 7)) * CDIM;
        ob[(size_t)r0 * CDIM] = __ldg(xb + g0off + o) + lo + buv;
        ob[(size_t)r1 * CDIM] = __ldg(xb + g1off + o) + hi + buv;
    }
}

// ---------------- launcher ----------------
extern "C" void kernel_launch(void* const* d_in, const int* in_sizes, int n_in,
                              void* d_out, int out_size) {
    const float* z  = (const float*)d_in[0];
    const float* x  = (const float*)d_in[1];
    const float* Wd = (const float*)d_in[2];
    const float* bd = (const float*)d_in[3];
    const float* Wu = (const float*)d_in[4];
    const float* bu = (const float*)d_in[5];
    float* out = (float*)d_out;

    k_transpose<<<256, 256>>>(Wd, Wu);
    k_zmax<<<BATCH, 256>>>(z);
    k_sim<<<BATCH * NWIN, 256>>>(x);
    k_topk<<<BATCH, 64>>>();

    static int smem_set = 0;
    // cudaFuncSetAttribute is idempotent and capture-safe (not a stream op);
    // call unconditionally to stay deterministic.
    (void)smem_set;
    cudaFuncSetAttribute(k_main, cudaFuncAttributeMaxDynamicSharedMemorySize, 65536);
    k_main<<<BATCH * TOPKN, 256, 65536>>>(x, bd, bu, out);
}